// round 7
// baseline (speedup 1.0000x reference)
#include <cuda_runtime.h>

#define FULL 0xffffffffu

// ---------------------------------------------------------------------------
// Half-warp (16 lanes) per item, 2 items/warp.
// Full 8-qubit state: 256 amps = 16 lanes x 16 local amps.
// Slot (lg, j): wire w<4 -> bit w of j (local), wire w>=4 -> bit (w-4) of lg.
// Product phase: psi_q, psi_k, value as three distributed 16-amp states.
// Cross phase: pairwise-fused commuting gates; CNOTs fused/folded;
// final rot folded into measurement observables.
// ---------------------------------------------------------------------------

__device__ __forceinline__ float2 shfl2x(float2 v, int m) {
    v.x = __shfl_xor_sync(FULL, v.x, m);
    v.y = __shfl_xor_sync(FULL, v.y, m);
    return v;
}
__device__ __forceinline__ float2 shfl2i(float2 v, int src) {  // within 16-group
    v.x = __shfl_sync(FULL, v.x, src, 16);
    v.y = __shfl_sync(FULL, v.y, src, 16);
    return v;
}
__device__ __forceinline__ float2 shfl2a(float2 v, int src) {  // absolute lane
    v.x = __shfl_sync(FULL, v.x, src);
    v.y = __shfl_sync(FULL, v.y, src);
    return v;
}
__device__ __forceinline__ float hred(float v) {
#pragma unroll
    for (int o = 8; o; o >>= 1) v += __shfl_xor_sync(FULL, v, o);
    return v;
}

// a_new = c*a + (-i s)*o
__device__ __forceinline__ float2 rxmix(float2 a, float2 o, float c, float s) {
    return make_float2(c * a.x + s * o.y, c * a.y - s * o.x);
}

// general unitary [[u00,u01],[-conj(u01),conj(u00)]], own bit b
__device__ __forceinline__ float2 genmix(float2 x, float2 t, float4 u, int b) {
    float cx = u.x, cy = b ? -u.y : u.y;
    float dx = b ? -u.z : u.z, dy = u.w;
    return make_float2(cx * x.x - cy * x.y + dx * t.x - dy * t.y,
                       cx * x.y + cy * x.x + dx * t.y + dy * t.x);
}

__device__ __forceinline__ float4 fuse_rx(float4 g, float c, float s) {
    float2 g00 = make_float2(g.x, g.y), g01 = make_float2(g.z, g.w);
    float2 u00 = rxmix(g00, g01, c, s);
    float2 u01 = rxmix(g01, g00, c, s);
    return make_float4(u00.x, u00.y, u01.x, u01.y);
}

// Fused pair of CRX gates with LOCAL controls (bits C0,C1 of j) and LANE
// targets (xor masks M0,M1). Gathers read pre-state; exact operator product.
template <int C0, int C1, int M0, int M1>
__device__ __forceinline__ void crx_lt2(float2* a, float cA, float sA, float cB, float sB) {
    const float AB = cA * cB, AsB = cA * sB, sAB = sA * cB, ss = sA * sB;
#pragma unroll
    for (int j = 0; j < 16; j++) {
        const int b0 = (j >> C0) & 1, b1 = (j >> C1) & 1;
        if (b0 && b1) {
            float2 t0 = shfl2x(a[j], M0);
            float2 t1 = shfl2x(a[j], M1);
            float2 t2 = shfl2x(a[j], M0 | M1);
            float2 x = a[j];
            a[j] = make_float2(AB * x.x + sAB * t0.y + AsB * t1.y - ss * t2.x,
                               AB * x.y - sAB * t0.x - AsB * t1.x - ss * t2.y);
        } else if (b0) {
            float2 t0 = shfl2x(a[j], M0);
            a[j] = rxmix(a[j], t0, cA, sA);
        } else if (b1) {
            float2 t1 = shfl2x(a[j], M1);
            a[j] = rxmix(a[j], t1, cB, sB);
        }
    }
}

// Fused pair of CRX gates with LANE controls (handled by caller via selected
// coefficients) and LOCAL targets (xor masks MT0, MT1). Branchless.
template <int MT0, int MT1>
__device__ __forceinline__ void crx_ll2(float2* a, float C0, float S0, float C1, float S1) {
    const float AB = C0 * C1, AsB = C0 * S1, sAB = S0 * C1, ss = S0 * S1;
#pragma unroll
    for (int j = 0; j < 16; j++) {
        if ((j & MT0) || (j & MT1)) continue;
        float2 x00 = a[j], x10 = a[j ^ MT0], x01 = a[j ^ MT1], x11 = a[j ^ MT0 ^ MT1];
        a[j] = make_float2(AB * x00.x + sAB * x10.y + AsB * x01.y - ss * x11.x,
                           AB * x00.y - sAB * x10.x - AsB * x01.x - ss * x11.y);
        a[j ^ MT0] = make_float2(AB * x10.x + sAB * x00.y + AsB * x11.y - ss * x01.x,
                                 AB * x10.y - sAB * x00.x - AsB * x11.x - ss * x01.y);
        a[j ^ MT1] = make_float2(AB * x01.x + sAB * x11.y + AsB * x00.y - ss * x10.x,
                                 AB * x01.y - sAB * x11.x - AsB * x00.x - ss * x10.y);
        a[j ^ MT0 ^ MT1] = make_float2(AB * x11.x + sAB * x01.y + AsB * x10.y - ss * x00.x,
                                       AB * x11.y - sAB * x01.x - AsB * x10.x - ss * x00.y);
    }
}

// ---------------------------------------------------------------------------

__global__ void __launch_bounds__(64, 8)
qa_fused(const float* __restrict__ x_text, const float* __restrict__ x_image,
         const float* __restrict__ W_text, const float* __restrict__ b_text,
         const float* __restrict__ W_image, const float* __restrict__ b_image,
         const float* __restrict__ qr, const float* __restrict__ qc,
         const float* __restrict__ kr, const float* __restrict__ kc,
         const float* __restrict__ vr, const float* __restrict__ vc,
         const float* __restrict__ cr, const float* __restrict__ cc,
         const float* __restrict__ cc2, const float* __restrict__ gates,
         float* __restrict__ out, int B, int IN) {
    // sf: [0..3] q L1, [4..7] q L2, [8..11] k L1, [12..15] k L2,
    //     [16..19] cross rot (unused directly), [20..23] v L1, [24..27] v L2
    __shared__ float4 sf[28];
    // scs: [0..7] q_crx, [8..15] k_crx, [16..23] c_crx, [24..31] c_crx2, [32..39] v_crx
    __shared__ float2 scs[40];
    __shared__ float sgates[4];
    // conjugated observables of the final cross rot layer, per wire:
    // szm[i] = (p, m.x, m.y, r); sn[i] = (n.x, n.y)
    __shared__ float4 szm[4];
    __shared__ float2 sn[4];

    for (int t = threadIdx.x; t < 76; t += blockDim.x) {
        if (t < 28) {
            int grp = t >> 2, i = t & 3;
            float a = 0.f, b = 0.f, c = 0.f;
            switch (grp) {
                case 0: a = qr[3 * i];      b = qr[3 * i + 1];      c = qr[3 * i + 2];      break;
                case 1: a = qr[12 + 3 * i]; b = qr[12 + 3 * i + 1]; c = qr[12 + 3 * i + 2]; break;
                case 2: a = kr[3 * i];      b = kr[3 * i + 1];      c = kr[3 * i + 2];      break;
                case 3: a = kr[12 + 3 * i]; b = kr[12 + 3 * i + 1]; c = kr[12 + 3 * i + 2]; break;
                case 4: a = cr[3 * i];      b = cr[3 * i + 1];      c = cr[3 * i + 2];      break;
                case 5: a = vr[3 * i];      b = vr[3 * i + 1];      c = vr[3 * i + 2];      break;
                case 6: a = vr[12 + 3 * i]; b = vr[12 + 3 * i + 1]; c = vr[12 + 3 * i + 2]; break;
            }
            float cb = cosf(0.5f * b), sb = sinf(0.5f * b);
            float sum = 0.5f * (a + c), dif = 0.5f * (a - c);
            sf[t] = make_float4(cb * cosf(sum), -cb * sinf(sum),
                                sb * sinf(dif), -sb * cosf(dif));
        } else if (t < 68) {
            int u = t - 28;
            float p;
            if (u < 8) p = qc[u];
            else if (u < 16) p = kc[u - 8];
            else if (u < 24) p = cc[u - 16];
            else if (u < 32) p = cc2[u - 24];
            else p = vc[u - 32];
            float s, c;
            sincosf(0.5f * p, &s, &c);
            scs[u] = make_float2(c, s);
        } else if (t < 72) {
            sgates[t - 68] = gates[t - 68];
        } else {
            // observables for cross final rot wire i: U = [[al,be],[-be*,al*]]
            int i = t - 72;
            float aa = cr[3 * i], b = cr[3 * i + 1], c = cr[3 * i + 2];
            float cb = cosf(0.5f * b), sb = sinf(0.5f * b);
            float sum = 0.5f * (aa + c), dif = 0.5f * (aa - c);
            float alx = cb * cosf(sum), aly = -cb * sinf(sum);
            float bex = sb * sinf(dif), bey = -sb * cosf(dif);
            float p = alx * alx + aly * aly - bex * bex - bey * bey;
            float mx = 2.f * (alx * bex + aly * bey);
            float my = 2.f * (alx * bey - aly * bex);
            float r = -2.f * (alx * bex - aly * bey);
            float nx = (alx * alx - aly * aly) - (bex * bex - bey * bey);
            float ny = -2.f * alx * aly - 2.f * bex * bey;
            szm[i] = make_float4(p, mx, my, r);
            sn[i] = make_float2(nx, ny);
        }
    }
    __syncthreads();

    const int lane = threadIdx.x & 31;
    const int half = lane >> 4;
    const int lg = lane & 15;
    const int gw = (int)((blockIdx.x * blockDim.x + threadIdx.x) >> 5);
    const int item = gw * 2 + half;
    const int itc = item < B ? item : (B - 1);

    // ---- projections ----
    float xq[4], xk[4];
    {
        const float* xt = x_text + (long)itc * IN;
        const float* xi = x_image + (long)itc * IN;
#pragma unroll
        for (int r = 0; r < 4; r++) {
            float pq = 0.f, pk = 0.f;
            for (int k = lg; k < IN; k += 16) {
                pq += xt[k] * __ldg(&W_text[r * IN + k]);
                pk += xi[k] * __ldg(&W_image[r * IN + k]);
            }
            xq[r] = hred(pq) + __ldg(&b_text[r]);
            xk[r] = hred(pk) + __ldg(&b_image[r]);
        }
    }

    // ---- product phase: three interleaved 16-amp rings (branchless) ----
    float2 vq = make_float2(lg == 0 ? 1.f : 0.f, 0.f);
    float2 vk = vq, vv = vq;

#pragma unroll
    for (int i = 0; i < 4; i++) {  // L1 with fused data RX
        float sq, cq, sk, ck;
        __sincosf(0.5f * xq[i], &sq, &cq);
        __sincosf(0.5f * xk[i], &sk, &ck);
        float4 uq = fuse_rx(sf[i], cq, sq);
        float4 uk = fuse_rx(sf[8 + i], ck, sk);
        float4 uv = fuse_rx(sf[20 + i], ck, sk);
        const int b = (lg >> i) & 1;
        float2 tq = shfl2x(vq, 1 << i);
        float2 tk = shfl2x(vk, 1 << i);
        float2 tv = shfl2x(vv, 1 << i);
        vq = genmix(vq, tq, uq, b);
        vk = genmix(vk, tk, uk, b);
        vv = genmix(vv, tv, uv, b);
    }
#pragma unroll
    for (int i = 0; i < 4; i++) {  // CRX rings (branchless select)
        const int m = 1 << ((i + 1) & 3);
        const bool p = (lg >> i) & 1;
        float cq = p ? scs[i].x : 1.f,      sq = p ? scs[i].y : 0.f;
        float ck = p ? scs[8 + i].x : 1.f,  sk = p ? scs[8 + i].y : 0.f;
        float cv = p ? scs[32 + i].x : 1.f, sv = p ? scs[32 + i].y : 0.f;
        float2 tq = shfl2x(vq, m), tk = shfl2x(vk, m), tv = shfl2x(vv, m);
        vq = rxmix(vq, tq, cq, sq);
        vk = rxmix(vk, tk, ck, sk);
        vv = rxmix(vv, tv, cv, sv);
    }
#pragma unroll
    for (int i = 0; i < 4; i++) {  // IsingXX rings
        const int m = (1 << i) | (1 << ((i + 1) & 3));
        float2 tq = shfl2x(vq, m), tk = shfl2x(vk, m), tv = shfl2x(vv, m);
        vq = rxmix(vq, tq, scs[4 + i].x, scs[4 + i].y);
        vk = rxmix(vk, tk, scs[12 + i].x, scs[12 + i].y);
        vv = rxmix(vv, tv, scs[36 + i].x, scs[36 + i].y);
    }
#pragma unroll
    for (int i = 0; i < 4; i++) {  // L2
        const int b = (lg >> i) & 1;
        float2 tq = shfl2x(vq, 1 << i);
        float2 tk = shfl2x(vk, 1 << i);
        float2 tv = shfl2x(vv, 1 << i);
        vq = genmix(vq, tq, sf[4 + i], b);
        vk = genmix(vk, tk, sf[12 + i], b);
        vv = genmix(vv, tv, sf[24 + i], b);
    }

    // ---- assemble full state: a[j] = psi_q[j] * psi_k[lg] ----
    float2 a[16];
#pragma unroll
    for (int j = 0; j < 16; j++) {
        float2 qj = shfl2i(vq, j);
        a[j] = make_float2(qj.x * vk.x - qj.y * vk.y,
                           qj.x * vk.y + qj.y * vk.x);
    }

    // ---- cross entanglers, fused pairwise ----
    // CRX(i,4+i): local ctrl i -> lane mask (1<<i)
    crx_lt2<0, 1, 1, 2>(a, scs[16].x, scs[16].y, scs[17].x, scs[17].y);
    crx_lt2<2, 3, 4, 8>(a, scs[18].x, scs[18].y, scs[19].x, scs[19].y);
    // CRX(4+i,i): lane ctrl bit i -> local mask (1<<i)
    {
        bool e0 = lg & 1, e1 = lg & 2;
        crx_ll2<1, 2>(a, e0 ? scs[20].x : 1.f, e0 ? scs[20].y : 0.f,
                         e1 ? scs[21].x : 1.f, e1 ? scs[21].y : 0.f);
        bool e2 = lg & 4, e3 = lg & 8;
        crx_ll2<4, 8>(a, e2 ? scs[22].x : 1.f, e2 ? scs[22].y : 0.f,
                         e3 ? scs[23].x : 1.f, e3 ? scs[23].y : 0.f);
    }
    // CRX2(i, ((i+1)&3)+4): local ctrl i -> lane mask (1<<((i+1)&3))
    crx_lt2<0, 1, 2, 4>(a, scs[24].x, scs[24].y, scs[25].x, scs[25].y);
    crx_lt2<2, 3, 8, 1>(a, scs[26].x, scs[26].y, scs[27].x, scs[27].y);
    // CRX2(4+i, (i+1)&3): lane ctrl bit i -> local mask (1<<((i+1)&3))
    {
        bool e0 = lg & 1, e1 = lg & 2;
        crx_ll2<2, 4>(a, e0 ? scs[28].x : 1.f, e0 ? scs[28].y : 0.f,
                         e1 ? scs[29].x : 1.f, e1 ? scs[29].y : 0.f);
        bool e2 = lg & 4, e3 = lg & 8;
        crx_ll2<8, 1>(a, e2 ? scs[30].x : 1.f, e2 ? scs[30].y : 0.f,
                         e3 ? scs[31].x : 1.f, e3 ? scs[31].y : 0.f);
    }
    // all 4 CNOT(i,4+i) fused: one dynamic-src shuffle stage
#pragma unroll
    for (int j = 0; j < 16; j++) {
        int src = (lane & 16) | (lg ^ j);
        a[j] = shfl2a(a[j], src);
    }
    // all 4 CNOT(4+i,i): FREE via basis relabel (slot j holds basis j^lg).
    // Final cross rot layer + measurement: folded into conjugated observables.

    float amp4[4];
    {
        float zacc[4], xacc[4];
#pragma unroll
        for (int w = 0; w < 4; w++) {
            const int m = 1 << w;
            const float4 zm = szm[w];
            const float2 nn = sn[w];
            const float sgn = ((lg >> w) & 1) ? -1.f : 1.f;
            float z = 0.f, x = 0.f;
#pragma unroll
            for (int j = 0; j < 16; j++) {
                if (j & m) continue;
                float2 e0 = a[j], e1 = a[j | m];
                float D = (e0.x * e0.x + e0.y * e0.y) - (e1.x * e1.x + e1.y * e1.y);
                float R = e0.x * e1.x + e0.y * e1.y;
                float I = e0.x * e1.y - e0.y * e1.x;
                D *= sgn;
                I *= sgn;
                z += zm.x * D + 2.f * (zm.y * R - zm.z * I);
                x += zm.w * D + 2.f * (nn.x * R - nn.y * I);
            }
            zacc[w] = z;
            xacc[w] = x;
        }
#pragma unroll
        for (int w = 0; w < 4; w++) {
            zacc[w] = hred(zacc[w]);
            xacc[w] = hred(xacc[w]);
        }
#pragma unroll
        for (int w = 0; w < 4; w++)
            amp4[w] = sqrtf(zacc[w] * zacc[w] + xacc[w] * xacc[w]);
    }

    // ---- value tail: amp-RX fused pairwise ----
    {
        float cc0[4], ss0[4];
#pragma unroll
        for (int i = 0; i < 4; i++) {
            float ang = tanhf(amp4[i]) * sgates[i];
            __sincosf(0.5f * ang, &ss0[i], &cc0[i]);
        }
        {   // wires 0,1 (masks 1,2)
            float AB = cc0[0] * cc0[1], AsB = cc0[0] * ss0[1],
                  sAB = ss0[0] * cc0[1], ss = ss0[0] * ss0[1];
            float2 t0 = shfl2x(vv, 1), t1 = shfl2x(vv, 2), t2 = shfl2x(vv, 3);
            vv = make_float2(AB * vv.x + sAB * t0.y + AsB * t1.y - ss * t2.x,
                             AB * vv.y - sAB * t0.x - AsB * t1.x - ss * t2.y);
        }
        {   // wires 2,3 (masks 4,8)
            float AB = cc0[2] * cc0[3], AsB = cc0[2] * ss0[3],
                  sAB = ss0[2] * cc0[3], ss = ss0[2] * ss0[3];
            float2 t0 = shfl2x(vv, 4), t1 = shfl2x(vv, 8), t2 = shfl2x(vv, 12);
            vv = make_float2(AB * vv.x + sAB * t0.y + AsB * t1.y - ss * t2.x,
                             AB * vv.y - sAB * t0.x - AsB * t1.x - ss * t2.y);
        }
    }
    // CNOT ring folded into measurement via basis permutation pi
    int pi = lg;
    pi ^= (pi & 1) << 1;
    pi ^= ((pi >> 1) & 1) << 2;
    pi ^= ((pi >> 2) & 1) << 3;
    pi ^= (pi >> 3) & 1;

    float zres[4], xres[4];
    {
        const float nv = vv.x * vv.x + vv.y * vv.y;
#pragma unroll
        for (int w = 0; w < 4; w++) {
            zres[w] = ((pi >> w) & 1) ? -nv : nv;
            int r = pi ^ (1 << w);
            r ^= (r >> 3) & 1;
            r ^= ((r >> 2) & 1) << 3;
            r ^= ((r >> 1) & 1) << 2;
            r ^= (r & 1) << 1;
            float2 t = shfl2a(vv, (lane & 16) | r);
            xres[w] = vv.x * t.x + vv.y * t.y;
        }
#pragma unroll
        for (int w = 0; w < 4; w++) {
            zres[w] = hred(zres[w]);
            xres[w] = hred(xres[w]);
        }
    }

    if (lg == 0 && item < B) {
        float4* o0 = (float4*)(out + (long)item * 8);
        o0[0] = make_float4(zres[0], zres[1], zres[2], zres[3]);
        o0[1] = make_float4(xres[0], xres[1], xres[2], xres[3]);
    }
}

// ---------------------------------------------------------------------------

extern "C" void kernel_launch(void* const* d_in, const int* in_sizes, int n_in,
                              void* d_out, int out_size) {
    const float* x_text  = (const float*)d_in[0];
    const float* x_image = (const float*)d_in[1];
    const float* W_text  = (const float*)d_in[2];
    const float* b_text  = (const float*)d_in[3];
    const float* W_image = (const float*)d_in[4];
    const float* b_image = (const float*)d_in[5];
    const float* q_rot   = (const float*)d_in[6];
    const float* q_crx   = (const float*)d_in[7];
    const float* k_rot   = (const float*)d_in[8];
    const float* k_crx   = (const float*)d_in[9];
    const float* v_rot   = (const float*)d_in[10];
    const float* v_crx   = (const float*)d_in[11];
    const float* c_rot   = (const float*)d_in[12];
    const float* c_crx   = (const float*)d_in[13];
    const float* c_crx2  = (const float*)d_in[14];
    const float* gates   = (const float*)d_in[15];

    int IN = in_sizes[2] / 4;   // W_text is [4, IN]
    int B  = in_sizes[0] / IN;  // x_text is [B, IN]

    int nwarps = (B + 1) / 2;   // 2 items per warp
    int threads = 64;
    int blocks = (nwarps * 32 + threads - 1) / threads;
    qa_fused<<<blocks, threads>>>(x_text, x_image, W_text, b_text, W_image, b_image,
                                  q_rot, q_crx, k_rot, k_crx, v_rot, v_crx,
                                  c_rot, c_crx, c_crx2, gates,
                                  (float*)d_out, B, IN);
}

// round 8
// speedup vs baseline: 1.6933x; 1.6933x over previous
#include <cuda_runtime.h>

#define FULL 0xffffffffu

// ---------------------------------------------------------------------------
// Half-warp (16 lanes) per item, 2 items/warp.
// Full 8-qubit state: 256 amps = 16 lanes x 16 local amps.
// Slot (lg, j): wire w<4 -> bit w of j (local), wire w>=4 -> bit (w-4) of lg.
// Product phase: psi_q, psi_k, value as three interleaved 16-amp states.
// Cross phase: unfused branchless gates; CNOT(i,4+i)x4 as ONE dynamic
// shuffle; CNOT(4+i,i)x4 free via basis relabel; final rot + measurement
// folded into conjugated observables.  (All folds verified in R7.)
// ---------------------------------------------------------------------------

__device__ __forceinline__ float2 shfl2x(float2 v, int m) {
    v.x = __shfl_xor_sync(FULL, v.x, m);
    v.y = __shfl_xor_sync(FULL, v.y, m);
    return v;
}
__device__ __forceinline__ float2 shfl2i(float2 v, int src) {  // within 16-group
    v.x = __shfl_sync(FULL, v.x, src, 16);
    v.y = __shfl_sync(FULL, v.y, src, 16);
    return v;
}
__device__ __forceinline__ float2 shfl2a(float2 v, int src) {  // absolute lane
    v.x = __shfl_sync(FULL, v.x, src);
    v.y = __shfl_sync(FULL, v.y, src);
    return v;
}
__device__ __forceinline__ float hred(float v) {
#pragma unroll
    for (int o = 8; o; o >>= 1) v += __shfl_xor_sync(FULL, v, o);
    return v;
}

// a_new = c*a + (-i s)*o
__device__ __forceinline__ float2 rxmix(float2 a, float2 o, float c, float s) {
    return make_float2(c * a.x + s * o.y, c * a.y - s * o.x);
}

// general unitary [[u00,u01],[-conj(u01),conj(u00)]], own bit b
__device__ __forceinline__ float2 genmix(float2 x, float2 t, float4 u, int b) {
    float cx = u.x, cy = b ? -u.y : u.y;
    float dx = b ? -u.z : u.z, dy = u.w;
    return make_float2(cx * x.x - cy * x.y + dx * t.x - dy * t.y,
                       cx * x.y + cy * x.x + dx * t.y + dy * t.x);
}

__device__ __forceinline__ float4 fuse_rx(float4 g, float c, float s) {
    float2 g00 = make_float2(g.x, g.y), g01 = make_float2(g.z, g.w);
    float2 u00 = rxmix(g00, g01, c, s);
    float2 u01 = rxmix(g01, g00, c, s);
    return make_float4(u00.x, u00.y, u01.x, u01.y);
}

// ---------------------------------------------------------------------------

__global__ void __launch_bounds__(64, 8)
qa_fused(const float* __restrict__ x_text, const float* __restrict__ x_image,
         const float* __restrict__ W_text, const float* __restrict__ b_text,
         const float* __restrict__ W_image, const float* __restrict__ b_image,
         const float* __restrict__ qr, const float* __restrict__ qc,
         const float* __restrict__ kr, const float* __restrict__ kc,
         const float* __restrict__ vr, const float* __restrict__ vc,
         const float* __restrict__ cr, const float* __restrict__ cc,
         const float* __restrict__ cc2, const float* __restrict__ gates,
         float* __restrict__ out, int B, int IN) {
    // sf: [0..3] q L1, [4..7] q L2, [8..11] k L1, [12..15] k L2,
    //     [16..19] (unused, kept for indexing), [20..23] v L1, [24..27] v L2
    __shared__ float4 sf[28];
    // scs: [0..7] q_crx, [8..15] k_crx, [16..23] c_crx, [24..31] c_crx2, [32..39] v_crx
    __shared__ float2 scs[40];
    __shared__ float sgates[4];
    // conjugated observables of the final cross rot layer, per wire:
    // szm[i] = (p, m.x, m.y, r); sn[i] = (n.x, n.y)
    __shared__ float4 szm[4];
    __shared__ float2 sn[4];

    for (int t = threadIdx.x; t < 76; t += blockDim.x) {
        if (t < 28) {
            int grp = t >> 2, i = t & 3;
            float a = 0.f, b = 0.f, c = 0.f;
            switch (grp) {
                case 0: a = qr[3 * i];      b = qr[3 * i + 1];      c = qr[3 * i + 2];      break;
                case 1: a = qr[12 + 3 * i]; b = qr[12 + 3 * i + 1]; c = qr[12 + 3 * i + 2]; break;
                case 2: a = kr[3 * i];      b = kr[3 * i + 1];      c = kr[3 * i + 2];      break;
                case 3: a = kr[12 + 3 * i]; b = kr[12 + 3 * i + 1]; c = kr[12 + 3 * i + 2]; break;
                case 4: a = cr[3 * i];      b = cr[3 * i + 1];      c = cr[3 * i + 2];      break;
                case 5: a = vr[3 * i];      b = vr[3 * i + 1];      c = vr[3 * i + 2];      break;
                case 6: a = vr[12 + 3 * i]; b = vr[12 + 3 * i + 1]; c = vr[12 + 3 * i + 2]; break;
            }
            float cb = cosf(0.5f * b), sb = sinf(0.5f * b);
            float sum = 0.5f * (a + c), dif = 0.5f * (a - c);
            sf[t] = make_float4(cb * cosf(sum), -cb * sinf(sum),
                                sb * sinf(dif), -sb * cosf(dif));
        } else if (t < 68) {
            int u = t - 28;
            float p;
            if (u < 8) p = qc[u];
            else if (u < 16) p = kc[u - 8];
            else if (u < 24) p = cc[u - 16];
            else if (u < 32) p = cc2[u - 24];
            else p = vc[u - 32];
            float s, c;
            sincosf(0.5f * p, &s, &c);
            scs[u] = make_float2(c, s);
        } else if (t < 72) {
            sgates[t - 68] = gates[t - 68];
        } else {
            // conjugated observables for cross final rot wire i
            int i = t - 72;
            float aa = cr[3 * i], b = cr[3 * i + 1], c = cr[3 * i + 2];
            float cb = cosf(0.5f * b), sb = sinf(0.5f * b);
            float sum = 0.5f * (aa + c), dif = 0.5f * (aa - c);
            float alx = cb * cosf(sum), aly = -cb * sinf(sum);
            float bex = sb * sinf(dif), bey = -sb * cosf(dif);
            float p = alx * alx + aly * aly - bex * bex - bey * bey;
            float mx = 2.f * (alx * bex + aly * bey);
            float my = 2.f * (alx * bey - aly * bex);
            float r = -2.f * (alx * bex - aly * bey);
            float nx = (alx * alx - aly * aly) - (bex * bex - bey * bey);
            float ny = -2.f * alx * aly - 2.f * bex * bey;
            szm[i] = make_float4(p, mx, my, r);
            sn[i] = make_float2(nx, ny);
        }
    }
    __syncthreads();

    const int lane = threadIdx.x & 31;
    const int half = lane >> 4;
    const int lg = lane & 15;
    const int gw = (int)((blockIdx.x * blockDim.x + threadIdx.x) >> 5);
    const int item = gw * 2 + half;
    const int itc = item < B ? item : (B - 1);

    // ---- projections (float2-vectorized, k-outer r-inner) ----
    float xq[4], xk[4];
    {
        const float2* xt2 = (const float2*)(x_text + (long)itc * IN);
        const float2* xi2 = (const float2*)(x_image + (long)itc * IN);
        const int hin = IN >> 1;  // IN is even (96)
        float pq[4] = {0.f, 0.f, 0.f, 0.f}, pk[4] = {0.f, 0.f, 0.f, 0.f};
        for (int k = lg; k < hin; k += 16) {
            float2 xa = __ldg(&xt2[k]);
            float2 xb = __ldg(&xi2[k]);
#pragma unroll
            for (int r = 0; r < 4; r++) {
                float2 wa = __ldg((const float2*)(W_text + r * IN) + k);
                float2 wb = __ldg((const float2*)(W_image + r * IN) + k);
                pq[r] += xa.x * wa.x + xa.y * wa.y;
                pk[r] += xb.x * wb.x + xb.y * wb.y;
            }
        }
#pragma unroll
        for (int r = 0; r < 4; r++) {
            xq[r] = hred(pq[r]) + __ldg(&b_text[r]);
            xk[r] = hred(pk[r]) + __ldg(&b_image[r]);
        }
    }

    // ---- product phase: three interleaved 16-amp rings (branchless) ----
    float2 vq = make_float2(lg == 0 ? 1.f : 0.f, 0.f);
    float2 vk = vq, vv = vq;

#pragma unroll
    for (int i = 0; i < 4; i++) {  // L1 with fused data RX
        float sq, cq, sk, ck;
        __sincosf(0.5f * xq[i], &sq, &cq);
        __sincosf(0.5f * xk[i], &sk, &ck);
        float4 uq = fuse_rx(sf[i], cq, sq);
        float4 uk = fuse_rx(sf[8 + i], ck, sk);
        float4 uv = fuse_rx(sf[20 + i], ck, sk);
        const int b = (lg >> i) & 1;
        float2 tq = shfl2x(vq, 1 << i);
        float2 tk = shfl2x(vk, 1 << i);
        float2 tv = shfl2x(vv, 1 << i);
        vq = genmix(vq, tq, uq, b);
        vk = genmix(vk, tk, uk, b);
        vv = genmix(vv, tv, uv, b);
    }
#pragma unroll
    for (int i = 0; i < 4; i++) {  // CRX rings (branchless select)
        const int m = 1 << ((i + 1) & 3);
        const bool p = (lg >> i) & 1;
        float cq = p ? scs[i].x : 1.f,      sq = p ? scs[i].y : 0.f;
        float ck = p ? scs[8 + i].x : 1.f,  sk = p ? scs[8 + i].y : 0.f;
        float cv = p ? scs[32 + i].x : 1.f, sv = p ? scs[32 + i].y : 0.f;
        float2 tq = shfl2x(vq, m), tk = shfl2x(vk, m), tv = shfl2x(vv, m);
        vq = rxmix(vq, tq, cq, sq);
        vk = rxmix(vk, tk, ck, sk);
        vv = rxmix(vv, tv, cv, sv);
    }
#pragma unroll
    for (int i = 0; i < 4; i++) {  // IsingXX rings
        const int m = (1 << i) | (1 << ((i + 1) & 3));
        float2 tq = shfl2x(vq, m), tk = shfl2x(vk, m), tv = shfl2x(vv, m);
        vq = rxmix(vq, tq, scs[4 + i].x, scs[4 + i].y);
        vk = rxmix(vk, tk, scs[12 + i].x, scs[12 + i].y);
        vv = rxmix(vv, tv, scs[36 + i].x, scs[36 + i].y);
    }
#pragma unroll
    for (int i = 0; i < 4; i++) {  // L2
        const int b = (lg >> i) & 1;
        float2 tq = shfl2x(vq, 1 << i);
        float2 tk = shfl2x(vk, 1 << i);
        float2 tv = shfl2x(vv, 1 << i);
        vq = genmix(vq, tq, sf[4 + i], b);
        vk = genmix(vk, tk, sf[12 + i], b);
        vv = genmix(vv, tv, sf[24 + i], b);
    }

    // ---- assemble full state: a[j] = psi_q[j] * psi_k[lg] ----
    float2 a[16];
#pragma unroll
    for (int j = 0; j < 16; j++) {
        float2 qj = shfl2i(vq, j);
        a[j] = make_float2(qj.x * vk.x - qj.y * vk.y,
                           qj.x * vk.y + qj.y * vk.x);
    }

    // ---- cross entanglers (unfused, branchless) ----
    // CRX(i, 4+i): local ctrl bit i -> lane mask (1<<i). j-test is compile-time.
#pragma unroll
    for (int i = 0; i < 4; i++) {
        const float c = scs[16 + i].x, s = scs[16 + i].y;
        const int ml = 1 << i;
#pragma unroll
        for (int j = 0; j < 16; j++)
            if ((j >> i) & 1) {
                float2 t = shfl2x(a[j], ml);
                a[j] = rxmix(a[j], t, c, s);
            }
    }
    // CRX(4+i, i): lane ctrl bit i -> local mask (1<<i). Branchless coeff select.
#pragma unroll
    for (int i = 0; i < 4; i++) {
        const bool e = (lg >> i) & 1;
        const float c = e ? scs[20 + i].x : 1.f, s = e ? scs[20 + i].y : 0.f;
        const int m = 1 << i;
#pragma unroll
        for (int j = 0; j < 16; j++)
            if (!(j & m)) {
                int j2 = j | m;
                float2 x = a[j], p = a[j2];
                a[j] = rxmix(x, p, c, s);
                a[j2] = rxmix(p, x, c, s);
            }
    }
    // CRX2(i, ((i+1)&3)+4): local ctrl i -> lane mask (1<<((i+1)&3))
#pragma unroll
    for (int i = 0; i < 4; i++) {
        const float c = scs[24 + i].x, s = scs[24 + i].y;
        const int ml = 1 << ((i + 1) & 3);
#pragma unroll
        for (int j = 0; j < 16; j++)
            if ((j >> i) & 1) {
                float2 t = shfl2x(a[j], ml);
                a[j] = rxmix(a[j], t, c, s);
            }
    }
    // CRX2(4+i, (i+1)&3): lane ctrl bit i -> local mask (1<<((i+1)&3)). Branchless.
#pragma unroll
    for (int i = 0; i < 4; i++) {
        const bool e = (lg >> i) & 1;
        const float c = e ? scs[28 + i].x : 1.f, s = e ? scs[28 + i].y : 0.f;
        const int m = 1 << ((i + 1) & 3);
#pragma unroll
        for (int j = 0; j < 16; j++)
            if (!(j & m)) {
                int j2 = j | m;
                float2 x = a[j], p = a[j2];
                a[j] = rxmix(x, p, c, s);
                a[j2] = rxmix(p, x, c, s);
            }
    }
    // all 4 CNOT(i,4+i) fused: one dynamic-src shuffle stage
#pragma unroll
    for (int j = 0; j < 16; j++) {
        int src = (lane & 16) | (lg ^ j);
        a[j] = shfl2a(a[j], src);
    }
    // all 4 CNOT(4+i,i): FREE via basis relabel (slot j holds basis j^lg).
    // Final cross rot layer + measurement folded into conjugated observables.

    float amp4[4];
    {
        float zacc[4], xacc[4];
#pragma unroll
        for (int w = 0; w < 4; w++) {
            const int m = 1 << w;
            const float4 zm = szm[w];
            const float2 nn = sn[w];
            const float sgn = ((lg >> w) & 1) ? -1.f : 1.f;
            float z = 0.f, x = 0.f;
#pragma unroll
            for (int j = 0; j < 16; j++) {
                if (j & m) continue;
                float2 e0 = a[j], e1 = a[j | m];
                float D = (e0.x * e0.x + e0.y * e0.y) - (e1.x * e1.x + e1.y * e1.y);
                float R = e0.x * e1.x + e0.y * e1.y;
                float I = e0.x * e1.y - e0.y * e1.x;
                D *= sgn;
                I *= sgn;
                z += zm.x * D + 2.f * (zm.y * R - zm.z * I);
                x += zm.w * D + 2.f * (nn.x * R - nn.y * I);
            }
            zacc[w] = z;
            xacc[w] = x;
        }
#pragma unroll
        for (int w = 0; w < 4; w++) {
            zacc[w] = hred(zacc[w]);
            xacc[w] = hred(xacc[w]);
        }
#pragma unroll
        for (int w = 0; w < 4; w++)
            amp4[w] = sqrtf(zacc[w] * zacc[w] + xacc[w] * xacc[w]);
    }

    // ---- value tail: amp-RX fused pairwise ----
    {
        float cc0[4], ss0[4];
#pragma unroll
        for (int i = 0; i < 4; i++) {
            float ang = tanhf(amp4[i]) * sgates[i];
            __sincosf(0.5f * ang, &ss0[i], &cc0[i]);
        }
        {   // wires 0,1 (masks 1,2)
            float AB = cc0[0] * cc0[1], AsB = cc0[0] * ss0[1],
                  sAB = ss0[0] * cc0[1], ss = ss0[0] * ss0[1];
            float2 t0 = shfl2x(vv, 1), t1 = shfl2x(vv, 2), t2 = shfl2x(vv, 3);
            vv = make_float2(AB * vv.x + sAB * t0.y + AsB * t1.y - ss * t2.x,
                             AB * vv.y - sAB * t0.x - AsB * t1.x - ss * t2.y);
        }
        {   // wires 2,3 (masks 4,8)
            float AB = cc0[2] * cc0[3], AsB = cc0[2] * ss0[3],
                  sAB = ss0[2] * cc0[3], ss = ss0[2] * ss0[3];
            float2 t0 = shfl2x(vv, 4), t1 = shfl2x(vv, 8), t2 = shfl2x(vv, 12);
            vv = make_float2(AB * vv.x + sAB * t0.y + AsB * t1.y - ss * t2.x,
                             AB * vv.y - sAB * t0.x - AsB * t1.x - ss * t2.y);
        }
    }
    // CNOT ring folded into measurement via basis permutation pi
    int pi = lg;
    pi ^= (pi & 1) << 1;
    pi ^= ((pi >> 1) & 1) << 2;
    pi ^= ((pi >> 2) & 1) << 3;
    pi ^= (pi >> 3) & 1;

    float zres[4], xres[4];
    {
        const float nv = vv.x * vv.x + vv.y * vv.y;
#pragma unroll
        for (int w = 0; w < 4; w++) {
            zres[w] = ((pi >> w) & 1) ? -nv : nv;
            int r = pi ^ (1 << w);
            r ^= (r >> 3) & 1;
            r ^= ((r >> 2) & 1) << 3;
            r ^= ((r >> 1) & 1) << 2;
            r ^= (r & 1) << 1;
            float2 t = shfl2a(vv, (lane & 16) | r);
            xres[w] = vv.x * t.x + vv.y * t.y;
        }
#pragma unroll
        for (int w = 0; w < 4; w++) {
            zres[w] = hred(zres[w]);
            xres[w] = hred(xres[w]);
        }
    }

    if (lg == 0 && item < B) {
        float4* o0 = (float4*)(out + (long)item * 8);
        o0[0] = make_float4(zres[0], zres[1], zres[2], zres[3]);
        o0[1] = make_float4(xres[0], xres[1], xres[2], xres[3]);
    }
}

// ---------------------------------------------------------------------------

extern "C" void kernel_launch(void* const* d_in, const int* in_sizes, int n_in,
                              void* d_out, int out_size) {
    const float* x_text  = (const float*)d_in[0];
    const float* x_image = (const float*)d_in[1];
    const float* W_text  = (const float*)d_in[2];
    const float* b_text  = (const float*)d_in[3];
    const float* W_image = (const float*)d_in[4];
    const float* b_image = (const float*)d_in[5];
    const float* q_rot   = (const float*)d_in[6];
    const float* q_crx   = (const float*)d_in[7];
    const float* k_rot   = (const float*)d_in[8];
    const float* k_crx   = (const float*)d_in[9];
    const float* v_rot   = (const float*)d_in[10];
    const float* v_crx   = (const float*)d_in[11];
    const float* c_rot   = (const float*)d_in[12];
    const float* c_crx   = (const float*)d_in[13];
    const float* c_crx2  = (const float*)d_in[14];
    const float* gates   = (const float*)d_in[15];

    int IN = in_sizes[2] / 4;   // W_text is [4, IN]
    int B  = in_sizes[0] / IN;  // x_text is [B, IN]

    int nwarps = (B + 1) / 2;   // 2 items per warp
    int threads = 64;
    int blocks = (nwarps * 32 + threads - 1) / threads;
    qa_fused<<<blocks, threads>>>(x_text, x_image, W_text, b_text, W_image, b_image,
                                  q_rot, q_crx, k_rot, k_crx, v_rot, v_crx,
                                  c_rot, c_crx, c_crx2, gates,
                                  (float*)d_out, B, IN);
}